// round 1
// baseline (speedup 1.0000x reference)
#include <cuda_runtime.h>
#include <cstdint>

// Radon transform, ray-driven bilinear, matching the JAX reference exactly
// (zero-padded sampling == reference's per-corner valid masking).
//
// x: (32, 1, 512, 512) f32   ->  out: (32, 1, 512, 180) f32
//
// Block = (u-tile of 128, angle, batch). Loops over 8 v-tiles of 64:
//   stage rotated-footprint bbox into SMEM (coalesced, zero-filled OOB),
//   gather+bilinear from SMEM, accumulate in registers, final warp reduce.

namespace {
constexpr int Hh = 512;
constexpr int Ww = 512;
constexpr int NA = 180;
constexpr int TU = 128;          // detector positions per block
constexpr int TV = 64;           // ray steps per staged tile
constexpr int THREADS = 256;     // 8 warps
// bbox span <= sqrt(127^2+63^2)=141.8 -> rows,cols <= 146, pitch(odd) <= 147
constexpr int SMEM_FLOATS = 146 * 147;
constexpr int SMEM_BYTES = SMEM_FLOATS * (int)sizeof(float);
}

__global__ __launch_bounds__(THREADS, 2)
void radon_kernel(const float* __restrict__ x, float* __restrict__ out) {
    extern __shared__ float sm[];
    const int tid  = threadIdx.x;
    const int lane = tid & 31;
    const int wid  = tid >> 5;
    const int u_t  = blockIdx.x;   // 0..3
    const int a    = blockIdx.y;   // 0..179
    const int n    = blockIdx.z;   // 0..31

    const float theta = (float)a * 0.017453292519943295f;
    float s, c;
    sincosf(theta, &s, &c);

    const int u0 = u_t * TU;
    const float fu_lo = (float)u0 - 255.5f;
    const float fu_hi = fu_lo + (float)(TU - 1);

    const float* __restrict__ img = x + (size_t)n * (size_t)(Hh * Ww);

    float acc[4] = {0.f, 0.f, 0.f, 0.f};

    const float dux =  32.0f * c;   // ix step per +32 u
    const float duy = -32.0f * s;   // iy step per +32 u
    const float dvx =   8.0f * s;   // ix step per +8 v
    const float dvy =   8.0f * c;   // iy step per +8 v

    for (int vt = 0; vt < Hh; vt += TV) {
        // --- bounding box of sample footprint for this (u,v) tile ---
        const float fv_lo = (float)vt - 255.5f;
        const float fv_hi = fv_lo + (float)(TV - 1);

        const float x00 = c * fu_lo + s * fv_lo, x01 = c * fu_lo + s * fv_hi;
        const float x10 = c * fu_hi + s * fv_lo, x11 = c * fu_hi + s * fv_hi;
        const float ixmin = fminf(fminf(x00, x01), fminf(x10, x11)) + 255.5f;
        const float ixmax = fmaxf(fmaxf(x00, x01), fmaxf(x10, x11)) + 255.5f;

        const float y00 = -s * fu_lo + c * fv_lo, y01 = -s * fu_lo + c * fv_hi;
        const float y10 = -s * fu_hi + c * fv_lo, y11 = -s * fu_hi + c * fv_hi;
        const float iymin = fminf(fminf(y00, y01), fminf(y10, y11)) + 255.5f;
        const float iymax = fmaxf(fmaxf(y00, y01), fmaxf(y10, y11)) + 255.5f;

        const int c_lo  = (int)floorf(ixmin) - 1;
        const int cols  = ((int)floorf(ixmax) + 2) - c_lo + 1;
        const int r_lo  = (int)floorf(iymin) - 1;
        const int rows  = ((int)floorf(iymax) + 2) - r_lo + 1;
        const int pitch = cols | 1;   // odd pitch: no systematic bank conflicts

        // --- stage bbox into SMEM, zero-filled outside image ---
        for (int r = wid; r < rows; r += 8) {
            const int gr = r_lo + r;
            const bool rok = ((unsigned)gr < (unsigned)Hh);
            const float* src = img + (size_t)gr * Ww;
            float* dst = sm + r * pitch;
            for (int cc = lane; cc < cols; cc += 32) {
                const int gc = c_lo + cc;
                float v = 0.0f;
                if (rok && ((unsigned)gc < (unsigned)Ww)) v = __ldg(src + gc);
                dst[cc] = v;
            }
        }
        __syncthreads();

        // --- gather + bilinear: warp wid handles v = vt + wid + 8k ---
        const float fu = (float)(u0 + lane) - 255.5f;
        const float fv = (float)(vt + wid) - 255.5f;
        float bx = fmaf(c, fu, fmaf(s, fv, 255.5f)) - (float)c_lo;
        float by = fmaf(-s, fu, fmaf(c, fv, 255.5f)) - (float)r_lo;

        #pragma unroll
        for (int k = 0; k < 8; ++k) {
            float ix = bx, iy = by;
            #pragma unroll
            for (int uq = 0; uq < 4; ++uq) {
                const float fx0 = floorf(ix);
                const float fy0 = floorf(iy);
                const float fx = ix - fx0;
                const float fy = iy - fy0;
                const int idx = (int)fy0 * pitch + (int)fx0;
                const float v00 = sm[idx];
                const float v01 = sm[idx + 1];
                const float v10 = sm[idx + pitch];
                const float v11 = sm[idx + pitch + 1];
                const float top = fmaf(fx, v01 - v00, v00);
                const float bot = fmaf(fx, v11 - v10, v10);
                acc[uq] += fmaf(fy, bot - top, top);
                ix += dux;
                iy += duy;
            }
            bx += dvx;
            by += dvy;
        }
        __syncthreads();   // SMEM reused by next stage / final reduce
    }

    // --- cross-warp reduction: 128 u-positions x 8 warps ---
    #pragma unroll
    for (int uq = 0; uq < 4; ++uq)
        sm[(uq * 32 + lane) * 8 + wid] = acc[uq];
    __syncthreads();

    if (tid < TU) {
        const float* p = sm + tid * 8;
        const float tot = ((p[0] + p[1]) + (p[2] + p[3])) +
                          ((p[4] + p[5]) + (p[6] + p[7]));
        // out[n, 0, u, a]
        out[((size_t)(n * Ww + (u0 + tid))) * NA + a] = tot;
    }
}

extern "C" void kernel_launch(void* const* d_in, const int* in_sizes, int n_in,
                              void* d_out, int out_size) {
    (void)in_sizes; (void)n_in; (void)out_size;
    const float* x = (const float*)d_in[0];
    float* out = (float*)d_out;

    cudaFuncSetAttribute(radon_kernel,
                         cudaFuncAttributeMaxDynamicSharedMemorySize,
                         SMEM_BYTES);

    dim3 grid(Ww / TU, NA, 32);   // (4, 180, 32)
    radon_kernel<<<grid, THREADS, SMEM_BYTES>>>(x, out);
}

// round 2
// speedup vs baseline: 1.8326x; 1.8326x over previous
#include <cuda_runtime.h>
#include <cstdint>

// Radon transform, ray-driven bilinear, matching the JAX reference exactly
// (zero-padded SMEM sampling == reference's per-corner valid masking).
//
// x: (32, 1, 512, 512) f32   ->  out: (32, 1, 512, 180) f32
//
// Block = (u-tile of 64, angle, batch image). Loops over 8 v-tiles of 64:
//   stage rotated-footprint bbox into SMEM (coalesced, zero-filled OOB),
//   gather+bilinear from SMEM, accumulate in registers, final warp reduce.
//
// R2 change vs R1: TU 128->64 (smem 86KB->35.7KB) + __launch_bounds__(256,4)
// (regs 128->64) so 4 blocks/SM = 32 warps, doubling occupancy — R1 was
// issue/latency-bound at occ=25%, issue=26%.

namespace {
constexpr int Hh = 512;
constexpr int Ww = 512;
constexpr int NA = 180;
constexpr int TU = 64;           // detector positions per block
constexpr int TV = 64;           // ray steps per staged tile
constexpr int THREADS = 256;     // 8 warps
// bbox: span <= 63*sqrt(2)=89.1 -> cols,rows <= 94, pitch(odd) <= 95
constexpr int SMEM_FLOATS = 94 * 95;
constexpr int SMEM_BYTES = SMEM_FLOATS * (int)sizeof(float);
}

__global__ __launch_bounds__(THREADS, 4)
void radon_kernel(const float* __restrict__ x, float* __restrict__ out) {
    extern __shared__ float sm[];
    const int tid  = threadIdx.x;
    const int lane = tid & 31;
    const int wid  = tid >> 5;
    const int u_t  = blockIdx.x;   // 0..7
    const int a    = blockIdx.y;   // 0..179
    const int n    = blockIdx.z;   // 0..31

    const float theta = (float)a * 0.017453292519943295f;
    float s, c;
    sincosf(theta, &s, &c);

    const int u0 = u_t * TU;
    const float fu_lo = (float)u0 - 255.5f;
    const float fu_hi = fu_lo + (float)(TU - 1);

    const float* __restrict__ img = x + (size_t)n * (size_t)(Hh * Ww);

    float acc0 = 0.f, acc1 = 0.f;

    const float dux =  32.0f * c;   // ix step per +32 u
    const float duy = -32.0f * s;   // iy step per +32 u
    const float dvx =   8.0f * s;   // ix step per +8 v
    const float dvy =   8.0f * c;   // iy step per +8 v

    for (int vt = 0; vt < Hh; vt += TV) {
        // --- bounding box of sample footprint for this (u,v) tile ---
        const float fv_lo = (float)vt - 255.5f;
        const float fv_hi = fv_lo + (float)(TV - 1);

        const float x00 = c * fu_lo + s * fv_lo, x01 = c * fu_lo + s * fv_hi;
        const float x10 = c * fu_hi + s * fv_lo, x11 = c * fu_hi + s * fv_hi;
        const float ixmin = fminf(fminf(x00, x01), fminf(x10, x11)) + 255.5f;
        const float ixmax = fmaxf(fmaxf(x00, x01), fmaxf(x10, x11)) + 255.5f;

        const float y00 = -s * fu_lo + c * fv_lo, y01 = -s * fu_lo + c * fv_hi;
        const float y10 = -s * fu_hi + c * fv_lo, y11 = -s * fu_hi + c * fv_hi;
        const float iymin = fminf(fminf(y00, y01), fminf(y10, y11)) + 255.5f;
        const float iymax = fmaxf(fmaxf(y00, y01), fmaxf(y10, y11)) + 255.5f;

        const int c_lo  = (int)floorf(ixmin) - 1;
        const int cols  = ((int)floorf(ixmax) + 2) - c_lo + 1;
        const int r_lo  = (int)floorf(iymin) - 1;
        const int rows  = ((int)floorf(iymax) + 2) - r_lo + 1;
        const int pitch = cols | 1;   // odd pitch: no systematic bank conflicts

        // --- stage bbox into SMEM, zero-filled outside image ---
        for (int r = wid; r < rows; r += 8) {
            const int gr = r_lo + r;
            const bool rok = ((unsigned)gr < (unsigned)Hh);
            const float* src = img + (size_t)gr * Ww;
            float* dst = sm + r * pitch;
            for (int cc = lane; cc < cols; cc += 32) {
                const int gc = c_lo + cc;
                float v = 0.0f;
                if (rok && ((unsigned)gc < (unsigned)Ww)) v = __ldg(src + gc);
                dst[cc] = v;
            }
        }
        __syncthreads();

        // --- gather + bilinear: warp wid handles v = vt + wid + 8k ---
        const float fu = (float)(u0 + lane) - 255.5f;
        const float fv = (float)(vt + wid) - 255.5f;
        float bx = fmaf(c, fu, fmaf(s, fv, 255.5f)) - (float)c_lo;
        float by = fmaf(-s, fu, fmaf(c, fv, 255.5f)) - (float)r_lo;

        #pragma unroll
        for (int k = 0; k < 8; ++k) {
            // uq = 0  (u = u0 + lane)
            {
                const float fx0 = floorf(bx);
                const float fy0 = floorf(by);
                const float fx = bx - fx0;
                const float fy = by - fy0;
                const int idx = (int)fy0 * pitch + (int)fx0;
                const float v00 = sm[idx];
                const float v01 = sm[idx + 1];
                const float v10 = sm[idx + pitch];
                const float v11 = sm[idx + pitch + 1];
                const float top = fmaf(fx, v01 - v00, v00);
                const float bot = fmaf(fx, v11 - v10, v10);
                acc0 += fmaf(fy, bot - top, top);
            }
            // uq = 1  (u = u0 + 32 + lane)
            {
                const float ix = bx + dux;
                const float iy = by + duy;
                const float fx0 = floorf(ix);
                const float fy0 = floorf(iy);
                const float fx = ix - fx0;
                const float fy = iy - fy0;
                const int idx = (int)fy0 * pitch + (int)fx0;
                const float v00 = sm[idx];
                const float v01 = sm[idx + 1];
                const float v10 = sm[idx + pitch];
                const float v11 = sm[idx + pitch + 1];
                const float top = fmaf(fx, v01 - v00, v00);
                const float bot = fmaf(fx, v11 - v10, v10);
                acc1 += fmaf(fy, bot - top, top);
            }
            bx += dvx;
            by += dvy;
        }
        __syncthreads();   // SMEM reused by next stage / final reduce
    }

    // --- cross-warp reduction: 64 u-positions x 8 warps ---
    sm[(lane)      * 8 + wid] = acc0;
    sm[(32 + lane) * 8 + wid] = acc1;
    __syncthreads();

    if (tid < TU) {
        const float* p = sm + tid * 8;
        const float tot = ((p[0] + p[1]) + (p[2] + p[3])) +
                          ((p[4] + p[5]) + (p[6] + p[7]));
        // out[n, 0, u, a]
        out[((size_t)(n * Ww + (u0 + tid))) * NA + a] = tot;
    }
}

extern "C" void kernel_launch(void* const* d_in, const int* in_sizes, int n_in,
                              void* d_out, int out_size) {
    (void)in_sizes; (void)n_in; (void)out_size;
    const float* x = (const float*)d_in[0];
    float* out = (float*)d_out;

    cudaFuncSetAttribute(radon_kernel,
                         cudaFuncAttributeMaxDynamicSharedMemorySize,
                         SMEM_BYTES);

    dim3 grid(Ww / TU, NA, 32);   // (8, 180, 32)
    radon_kernel<<<grid, THREADS, SMEM_BYTES>>>(x, out);
}

// round 3
// speedup vs baseline: 2.1309x; 1.1628x over previous
#include <cuda_runtime.h>
#include <cstdint>

// Radon transform, ray-driven bilinear, matching the JAX reference exactly
// (zero-filled SMEM sampling == reference's per-corner valid masking).
//
// x: (32, 1, 512, 512) f32   ->  out: (32, 1, 512, 180) f32
//
// Block = (u-tile of 64, angle, batch image). Loops over 8 v-tiles of 64:
//   stage rotated-footprint bbox into SMEM via cp.async (zero-fill OOB),
//   gather+bilinear from SMEM, accumulate in registers, final warp reduce.
//
// R3 changes vs R2 (issue/occupancy-bound at occ=49.6%, issue=50.5%):
//  - __launch_bounds__(256,6): 6 blocks/SM (48 warps, 75% occ); smem 35.7KB*6
//    = 214KB fits the 228KB carveout.
//  - cp.async zfill staging (no LDG->STS reg round-trip, no scoreboard stall).
//  - bilinear index computed in float (one F2I instead of two + IMAD).

namespace {
constexpr int Hh = 512;
constexpr int Ww = 512;
constexpr int NA = 180;
constexpr int TU = 64;           // detector positions per block
constexpr int TV = 64;           // ray steps per staged tile
constexpr int THREADS = 256;     // 8 warps
// bbox: span <= 63*sqrt(2)=89.1 -> cols,rows <= 94, pitch(odd) <= 95
constexpr int SMEM_FLOATS = 94 * 95;
constexpr int SMEM_BYTES = SMEM_FLOATS * (int)sizeof(float);
}

__device__ __forceinline__ void cp_async_zfill4(uint32_t dst_smem,
                                                const void* src_gmem,
                                                uint32_t src_size) {
    asm volatile("cp.async.ca.shared.global [%0], [%1], 4, %2;\n"
                 :: "r"(dst_smem), "l"(src_gmem), "r"(src_size));
}

__global__ __launch_bounds__(THREADS, 6)
void radon_kernel(const float* __restrict__ x, float* __restrict__ out) {
    extern __shared__ float sm[];
    const uint32_t sm_u32 = (uint32_t)__cvta_generic_to_shared(sm);
    const int tid  = threadIdx.x;
    const int lane = tid & 31;
    const int wid  = tid >> 5;
    const int u_t  = blockIdx.x;   // 0..7
    const int a    = blockIdx.y;   // 0..179
    const int n    = blockIdx.z;   // 0..31

    const float theta = (float)a * 0.017453292519943295f;
    float s, c;
    sincosf(theta, &s, &c);

    const int u0 = u_t * TU;
    const float fu_lo = (float)u0 - 255.5f;
    const float fu_hi = fu_lo + (float)(TU - 1);

    const float* __restrict__ img = x + (size_t)n * (size_t)(Hh * Ww);

    float acc0 = 0.f, acc1 = 0.f;

    const float dux =  32.0f * c;   // ix step per +32 u
    const float duy = -32.0f * s;   // iy step per +32 u
    const float dvx =   8.0f * s;   // ix step per +8 v
    const float dvy =   8.0f * c;   // iy step per +8 v

    for (int vt = 0; vt < Hh; vt += TV) {
        // --- bounding box of sample footprint for this (u,v) tile ---
        const float fv_lo = (float)vt - 255.5f;
        const float fv_hi = fv_lo + (float)(TV - 1);

        const float x00 = c * fu_lo + s * fv_lo, x01 = c * fu_lo + s * fv_hi;
        const float x10 = c * fu_hi + s * fv_lo, x11 = c * fu_hi + s * fv_hi;
        const float ixmin = fminf(fminf(x00, x01), fminf(x10, x11)) + 255.5f;
        const float ixmax = fmaxf(fmaxf(x00, x01), fmaxf(x10, x11)) + 255.5f;

        const float y00 = -s * fu_lo + c * fv_lo, y01 = -s * fu_lo + c * fv_hi;
        const float y10 = -s * fu_hi + c * fv_lo, y11 = -s * fu_hi + c * fv_hi;
        const float iymin = fminf(fminf(y00, y01), fminf(y10, y11)) + 255.5f;
        const float iymax = fmaxf(fmaxf(y00, y01), fmaxf(y10, y11)) + 255.5f;

        const int c_lo  = (int)floorf(ixmin) - 1;
        const int cols  = ((int)floorf(ixmax) + 2) - c_lo + 1;
        const int r_lo  = (int)floorf(iymin) - 1;
        const int rows  = ((int)floorf(iymax) + 2) - r_lo + 1;
        const int pitch = cols | 1;   // odd pitch: no systematic bank conflicts

        // --- stage bbox into SMEM via cp.async, zero-filled outside image ---
        for (int r = wid; r < rows; r += 8) {
            const int gr = r_lo + r;
            const bool rok = ((unsigned)gr < (unsigned)Hh);
            const int grc = min(max(gr, 0), Hh - 1);
            const float* src_row = img + (size_t)grc * Ww;
            const uint32_t dst_row = sm_u32 + (uint32_t)(r * pitch) * 4u;
            for (int cc = lane; cc < cols; cc += 32) {
                const int gc = c_lo + cc;
                const bool ok = rok && ((unsigned)gc < (unsigned)Ww);
                const int gcc = min(max(gc, 0), Ww - 1);
                cp_async_zfill4(dst_row + (uint32_t)cc * 4u,
                                src_row + gcc, ok ? 4u : 0u);
            }
        }
        asm volatile("cp.async.commit_group;\n" ::: "memory");
        asm volatile("cp.async.wait_group 0;\n" ::: "memory");
        __syncthreads();

        // --- gather + bilinear: warp wid handles v = vt + wid + 8k ---
        const float fpitch = (float)pitch;
        const float fu = (float)(u0 + lane) - 255.5f;
        const float fv = (float)(vt + wid) - 255.5f;
        float bx = fmaf(c, fu, fmaf(s, fv, 255.5f)) - (float)c_lo;
        float by = fmaf(-s, fu, fmaf(c, fv, 255.5f)) - (float)r_lo;

        #pragma unroll
        for (int k = 0; k < 8; ++k) {
            // uq = 0  (u = u0 + lane)
            {
                const float fx0 = floorf(bx);
                const float fy0 = floorf(by);
                const float fx = bx - fx0;
                const float fy = by - fy0;
                // fy0*pitch + fx0 < 94*95 -> exact in fp32
                const int idx = (int)fmaf(fy0, fpitch, fx0);
                const float v00 = sm[idx];
                const float v01 = sm[idx + 1];
                const float v10 = sm[idx + pitch];
                const float v11 = sm[idx + pitch + 1];
                const float top = fmaf(fx, v01 - v00, v00);
                const float bot = fmaf(fx, v11 - v10, v10);
                acc0 += fmaf(fy, bot - top, top);
            }
            // uq = 1  (u = u0 + 32 + lane)
            {
                const float ix = bx + dux;
                const float iy = by + duy;
                const float fx0 = floorf(ix);
                const float fy0 = floorf(iy);
                const float fx = ix - fx0;
                const float fy = iy - fy0;
                const int idx = (int)fmaf(fy0, fpitch, fx0);
                const float v00 = sm[idx];
                const float v01 = sm[idx + 1];
                const float v10 = sm[idx + pitch];
                const float v11 = sm[idx + pitch + 1];
                const float top = fmaf(fx, v01 - v00, v00);
                const float bot = fmaf(fx, v11 - v10, v10);
                acc1 += fmaf(fy, bot - top, top);
            }
            bx += dvx;
            by += dvy;
        }
        __syncthreads();   // SMEM reused by next stage / final reduce
    }

    // --- cross-warp reduction: 64 u-positions x 8 warps ---
    sm[(lane)      * 8 + wid] = acc0;
    sm[(32 + lane) * 8 + wid] = acc1;
    __syncthreads();

    if (tid < TU) {
        const float* p = sm + tid * 8;
        const float tot = ((p[0] + p[1]) + (p[2] + p[3])) +
                          ((p[4] + p[5]) + (p[6] + p[7]));
        // out[n, 0, u, a]
        out[((size_t)(n * Ww + (u0 + tid))) * NA + a] = tot;
    }
}

extern "C" void kernel_launch(void* const* d_in, const int* in_sizes, int n_in,
                              void* d_out, int out_size) {
    (void)in_sizes; (void)n_in; (void)out_size;
    const float* x = (const float*)d_in[0];
    float* out = (float*)d_out;

    cudaFuncSetAttribute(radon_kernel,
                         cudaFuncAttributeMaxDynamicSharedMemorySize,
                         SMEM_BYTES);

    dim3 grid(Ww / TU, NA, 32);   // (8, 180, 32)
    radon_kernel<<<grid, THREADS, SMEM_BYTES>>>(x, out);
}

// round 4
// speedup vs baseline: 4.1884x; 1.9656x over previous
#include <cuda_runtime.h>
#include <cstdint>

// Radon transform, ray-driven bilinear, matching the JAX reference
// (zero-filled SMEM sampling == reference's per-corner valid masking).
//
// x: (32, 1, 512, 512) f32   ->  out: (32, 1, 512, 180) f32
//
// R4 key change: 90-degree symmetry. For theta' = theta + 90deg:
//   sample_{theta'}(u=b, v=a) == sample_theta(u=a, v=511-b)   (exact algebra)
// so the theta-sampled rotated image gives BOTH outputs:
//   sino[theta][u]    = row sums  (over v)
//   sino[theta+90][b] = column sums (over u) at v = 511-b
// => 90 angle-blocks instead of 180: half the samples, half the staging.
//
// Block = (angle a in [0,90), image n). Loops over 8 u-strips x 8 v-tiles:
//   stage rotated-footprint bbox into SMEM via cp.async (zero-fill OOB),
//   gather+bilinear; u-sums in regs (smem-reduced per strip), v-sums via
//   warp shuffle reduce into smem vsum[512] (warp wid owns v%8==wid).

namespace {
constexpr int Hh = 512;
constexpr int Ww = 512;
constexpr int NA = 180;
constexpr int TT = 64;            // tile size in u and v
constexpr int PITCH = 95;         // fixed odd pitch; bbox cols,rows <= 94
constexpr int TILE_FLOATS = 94 * PITCH;          // 8930
constexpr int THREADS = 256;                     // 8 warps
constexpr int SCRATCH_FLOATS = 64 * 8;           // u-strip reduce
constexpr int SMEM_FLOATS = TILE_FLOATS + SCRATCH_FLOATS + 512;
constexpr int SMEM_BYTES = SMEM_FLOATS * (int)sizeof(float);
}

__device__ __forceinline__ void cp_async_zfill4(uint32_t dst_smem,
                                                const void* src_gmem,
                                                uint32_t src_size) {
    asm volatile("cp.async.ca.shared.global [%0], [%1], 4, %2;\n"
                 :: "r"(dst_smem), "l"(src_gmem), "r"(src_size));
}

__global__ __launch_bounds__(THREADS, 5)
void radon_kernel(const float* __restrict__ x, float* __restrict__ out) {
    extern __shared__ float sm[];
    float* tile    = sm;
    float* scratch = sm + TILE_FLOATS;
    float* vsum    = scratch + SCRATCH_FLOATS;
    const uint32_t tile_u32 = (uint32_t)__cvta_generic_to_shared(tile);

    const int tid  = threadIdx.x;
    const int lane = tid & 31;
    const int wid  = tid >> 5;
    const int a    = blockIdx.x;   // 0..89
    const int n    = blockIdx.y;   // 0..31

    const float theta = (float)a * 0.017453292519943295f;
    float s, c;
    sincosf(theta, &s, &c);

    const float* __restrict__ img = x + (size_t)n * (size_t)(Hh * Ww);

    // zero v-accumulator (ordered before first use by first phase's barrier)
    for (int i = tid; i < 512; i += THREADS) vsum[i] = 0.0f;

    const float dux =  32.0f * c;   // ix step per +32 u
    const float duy = -32.0f * s;   // iy step per +32 u
    const float dvx =   8.0f * s;   // ix step per +8 v
    const float dvy =   8.0f * c;   // iy step per +8 v

    for (int ut = 0; ut < 8; ++ut) {
        const int u0 = ut * TT;
        const float fu_lo = (float)u0 - 255.5f;
        const float fu_hi = fu_lo + (float)(TT - 1);
        float acc0 = 0.f, acc1 = 0.f;

        for (int vt = 0; vt < Hh; vt += TT) {
            // --- bounding box of sample footprint for this (u,v) tile ---
            const float fv_lo = (float)vt - 255.5f;
            const float fv_hi = fv_lo + (float)(TT - 1);

            const float x00 = c * fu_lo + s * fv_lo, x01 = c * fu_lo + s * fv_hi;
            const float x10 = c * fu_hi + s * fv_lo, x11 = c * fu_hi + s * fv_hi;
            const float ixmin = fminf(fminf(x00, x01), fminf(x10, x11)) + 255.5f;
            const float ixmax = fmaxf(fmaxf(x00, x01), fmaxf(x10, x11)) + 255.5f;

            const float y00 = -s * fu_lo + c * fv_lo, y01 = -s * fu_lo + c * fv_hi;
            const float y10 = -s * fu_hi + c * fv_lo, y11 = -s * fu_hi + c * fv_hi;
            const float iymin = fminf(fminf(y00, y01), fminf(y10, y11)) + 255.5f;
            const float iymax = fmaxf(fmaxf(y00, y01), fmaxf(y10, y11)) + 255.5f;

            const int c_lo = (int)floorf(ixmin) - 1;
            const int cols = ((int)floorf(ixmax) + 2) - c_lo + 1;   // <= 94
            const int r_lo = (int)floorf(iymin) - 1;
            const int rows = ((int)floorf(iymax) + 2) - r_lo + 1;   // <= 94

            // --- stage bbox into SMEM via cp.async, zero-fill outside image ---
            for (int r = wid; r < rows; r += 8) {
                const int gr = r_lo + r;
                const bool rok = ((unsigned)gr < (unsigned)Hh);
                const int grc = min(max(gr, 0), Hh - 1);
                const float* src_row = img + (size_t)grc * Ww;
                const uint32_t dst_row = tile_u32 + (uint32_t)(r * PITCH) * 4u;
                for (int cc = lane; cc < cols; cc += 32) {
                    const int gc = c_lo + cc;
                    const bool ok = rok && ((unsigned)gc < (unsigned)Ww);
                    const int gcc = min(max(gc, 0), Ww - 1);
                    cp_async_zfill4(dst_row + (uint32_t)cc * 4u,
                                    src_row + gcc, ok ? 4u : 0u);
                }
            }
            asm volatile("cp.async.commit_group;\n" ::: "memory");
            asm volatile("cp.async.wait_group 0;\n" ::: "memory");
            __syncthreads();

            // --- gather + bilinear: warp wid handles v = vt + wid + 8k ---
            const float fu = (float)(u0 + lane) - 255.5f;
            const float fv = (float)(vt + wid) - 255.5f;
            float bx = fmaf(c, fu, fmaf(s, fv, 255.5f)) - (float)c_lo;
            float by = fmaf(-s, fu, fmaf(c, fv, 255.5f)) - (float)r_lo;

            #pragma unroll
            for (int k = 0; k < 8; ++k) {
                float s0, s1;
                {   // u = u0 + lane
                    const float fx0 = floorf(bx);
                    const float fy0 = floorf(by);
                    const float fx = bx - fx0;
                    const float fy = by - fy0;
                    const int idx = (int)fmaf(fy0, (float)PITCH, fx0);
                    const float v00 = tile[idx];
                    const float v01 = tile[idx + 1];
                    const float v10 = tile[idx + PITCH];
                    const float v11 = tile[idx + PITCH + 1];
                    const float top = fmaf(fx, v01 - v00, v00);
                    const float bot = fmaf(fx, v11 - v10, v10);
                    s0 = fmaf(fy, bot - top, top);
                }
                {   // u = u0 + 32 + lane
                    const float ix = bx + dux;
                    const float iy = by + duy;
                    const float fx0 = floorf(ix);
                    const float fy0 = floorf(iy);
                    const float fx = ix - fx0;
                    const float fy = iy - fy0;
                    const int idx = (int)fmaf(fy0, (float)PITCH, fx0);
                    const float v00 = tile[idx];
                    const float v01 = tile[idx + 1];
                    const float v10 = tile[idx + PITCH];
                    const float v11 = tile[idx + PITCH + 1];
                    const float top = fmaf(fx, v01 - v00, v00);
                    const float bot = fmaf(fx, v11 - v10, v10);
                    s1 = fmaf(fy, bot - top, top);
                }
                acc0 += s0;
                acc1 += s1;

                // v-sum across the 64 u's of this tile at v = vt + wid + 8k
                float pv = s0 + s1;
                #pragma unroll
                for (int m = 16; m > 0; m >>= 1)
                    pv += __shfl_xor_sync(0xffffffffu, pv, m);
                if (lane == 0) vsum[vt + wid + 8 * k] += pv;

                bx += dvx;
                by += dvy;
            }
            __syncthreads();   // tile reused by next stage
        }

        // --- u-strip reduction: 64 u-positions x 8 warps -> out[.., a] ---
        scratch[lane * 8 + wid]        = acc0;
        scratch[(32 + lane) * 8 + wid] = acc1;
        __syncthreads();
        if (tid < TT) {
            const float* p = scratch + tid * 8;
            const float tot = ((p[0] + p[1]) + (p[2] + p[3])) +
                              ((p[4] + p[5]) + (p[6] + p[7]));
            out[((size_t)(n * Ww + (u0 + tid))) * NA + a] = tot;
        }
        __syncthreads();
    }

    // --- paired angle: sino[a+90][b] = vsum[511 - b] ---
    for (int i = tid; i < 512; i += THREADS)
        out[((size_t)(n * Ww + (511 - i))) * NA + (a + 90)] = vsum[i];
}

extern "C" void kernel_launch(void* const* d_in, const int* in_sizes, int n_in,
                              void* d_out, int out_size) {
    (void)in_sizes; (void)n_in; (void)out_size;
    const float* x = (const float*)d_in[0];
    float* out = (float*)d_out;

    cudaFuncSetAttribute(radon_kernel,
                         cudaFuncAttributeMaxDynamicSharedMemorySize,
                         SMEM_BYTES);

    dim3 grid(90, 32);   // (angle pair, image)
    radon_kernel<<<grid, THREADS, SMEM_BYTES>>>(x, out);
}

// round 5
// speedup vs baseline: 5.9981x; 1.4321x over previous
#include <cuda_runtime.h>
#include <cstdint>

// Radon transform, ray-driven bilinear, matching the JAX reference
// (zero-filled SMEM sampling == reference's per-corner valid masking).
//
// x: (32, 1, 512, 512) f32   ->  out: (32, 1, 512, 180) f32
//
// 90-degree symmetry (R4): theta-sampled rotated image gives BOTH
//   sino[theta][u]    = row sums  (over v)
//   sino[theta+90][b] = column sums (over u) at v = 511-b
//
// R5 changes vs R4 (issue=72%, L1=74.5%, occ=57.8%):
//  - 6 blocks/SM: u-reduce scratch aliased into tile region -> smem 36.9KB,
//    __launch_bounds__(256,6) (42 regs). occ ~70%.
//  - staging fast path for fully-interior bboxes: 2 warp-instr / 32 elems
//    (lane-hoisted addresses, immediate offsets, no clamps/masks).
//  - generic staging path: row-level rok poisoning -> single unsigned ISETP.

namespace {
constexpr int Hh = 512;
constexpr int Ww = 512;
constexpr int NA = 180;
constexpr int TT = 64;            // tile size in u and v
constexpr int PITCH = 95;         // fixed odd pitch; bbox cols,rows <= 94
constexpr int TILE_FLOATS = 94 * PITCH;          // 8930
constexpr int THREADS = 256;                     // 8 warps
constexpr int SMEM_FLOATS = TILE_FLOATS + 512;   // tile (+aliased scratch) + vsum
constexpr int SMEM_BYTES = SMEM_FLOATS * (int)sizeof(float);
}

__device__ __forceinline__ void cp_async4(uint32_t dst_smem, const void* src) {
    asm volatile("cp.async.ca.shared.global [%0], [%1], 4;\n"
                 :: "r"(dst_smem), "l"(src));
}
__device__ __forceinline__ void cp_async_zfill4(uint32_t dst_smem,
                                                const void* src,
                                                uint32_t src_size) {
    asm volatile("cp.async.ca.shared.global [%0], [%1], 4, %2;\n"
                 :: "r"(dst_smem), "l"(src), "r"(src_size));
}

__global__ __launch_bounds__(THREADS, 6)
void radon_kernel(const float* __restrict__ x, float* __restrict__ out) {
    extern __shared__ float sm[];
    float* tile = sm;                       // 8930 floats; scratch aliases this
    float* vsum = sm + TILE_FLOATS;         // 512 floats, persistent
    const uint32_t tile_u32 = (uint32_t)__cvta_generic_to_shared(tile);

    const int tid  = threadIdx.x;
    const int lane = tid & 31;
    const int wid  = tid >> 5;
    const int a    = blockIdx.x;   // 0..89
    const int n    = blockIdx.y;   // 0..31

    const float theta = (float)a * 0.017453292519943295f;
    float s, c;
    sincosf(theta, &s, &c);

    const float* __restrict__ img = x + (size_t)n * (size_t)(Hh * Ww);

    // zero v-accumulator (ordered before first gather by the staging barrier)
    for (int i = tid; i < 512; i += THREADS) vsum[i] = 0.0f;

    const float dux =  32.0f * c;   // ix step per +32 u
    const float duy = -32.0f * s;   // iy step per +32 u
    const float dvx =   8.0f * s;   // ix step per +8 v
    const float dvy =   8.0f * c;   // iy step per +8 v

    for (int ut = 0; ut < 8; ++ut) {
        const int u0 = ut * TT;
        const float fu_lo = (float)u0 - 255.5f;
        const float fu_hi = fu_lo + (float)(TT - 1);
        float acc0 = 0.f, acc1 = 0.f;

        for (int vt = 0; vt < Hh; vt += TT) {
            // --- bounding box of sample footprint for this (u,v) tile ---
            const float fv_lo = (float)vt - 255.5f;
            const float fv_hi = fv_lo + (float)(TT - 1);

            const float x00 = c * fu_lo + s * fv_lo, x01 = c * fu_lo + s * fv_hi;
            const float x10 = c * fu_hi + s * fv_lo, x11 = c * fu_hi + s * fv_hi;
            const float ixmin = fminf(fminf(x00, x01), fminf(x10, x11)) + 255.5f;
            const float ixmax = fmaxf(fmaxf(x00, x01), fmaxf(x10, x11)) + 255.5f;

            const float y00 = -s * fu_lo + c * fv_lo, y01 = -s * fu_lo + c * fv_hi;
            const float y10 = -s * fu_hi + c * fv_lo, y11 = -s * fu_hi + c * fv_hi;
            const float iymin = fminf(fminf(y00, y01), fminf(y10, y11)) + 255.5f;
            const float iymax = fmaxf(fmaxf(y00, y01), fmaxf(y10, y11)) + 255.5f;

            const int c_lo = (int)floorf(ixmin) - 1;
            const int cols = ((int)floorf(ixmax) + 2) - c_lo + 1;   // <= 94
            const int r_lo = (int)floorf(iymin) - 1;
            const int rows = ((int)floorf(iymax) + 2) - r_lo + 1;   // <= 94

            // --- stage bbox into SMEM via cp.async ---
            const bool interior = (c_lo >= 0) & (c_lo + cols <= Ww) &
                                  (r_lo >= 0) & (r_lo + rows <= Hh);
            if (interior) {
                // fast path: no clamps, no masks; lane-hoisted addresses
                const float* src0 = img + (size_t)(r_lo + wid) * Ww + c_lo + lane;
                uint32_t dst0 = tile_u32 + (uint32_t)((wid * PITCH + lane) * 4);
                for (int r = wid; r < rows; r += 8) {
                    #pragma unroll
                    for (int t = 0; t < 3; ++t)
                        if (lane + 32 * t < cols)
                            cp_async4(dst0 + 128u * t, src0 + 32 * t);
                    src0 += 8 * Ww;
                    dst0 += 8 * PITCH * 4;
                }
            } else {
                for (int r = wid; r < rows; r += 8) {
                    const int gr = r_lo + r;
                    const bool rok = ((unsigned)gr < (unsigned)Hh);
                    // poison columns when the row is OOB: ISETP fails for all cc
                    const int c_lo_eff = rok ? c_lo : 0x40000000;
                    const int grc = min(max(gr, 0), Hh - 1);
                    const float* src_row = img + (size_t)grc * Ww;
                    const uint32_t dst_row =
                        tile_u32 + (uint32_t)(r * PITCH) * 4u;
                    #pragma unroll
                    for (int t = 0; t < 3; ++t) {
                        const int cc = lane + 32 * t;
                        if (cc < cols) {
                            const int gc = c_lo_eff + cc;
                            const bool ok = ((unsigned)gc < (unsigned)Ww);
                            const int gcc = min(max(gc, 0), Ww - 1);
                            cp_async_zfill4(dst_row + (uint32_t)cc * 4u,
                                            src_row + gcc, ok ? 4u : 0u);
                        }
                    }
                }
            }
            asm volatile("cp.async.commit_group;\n" ::: "memory");
            asm volatile("cp.async.wait_group 0;\n" ::: "memory");
            __syncthreads();

            // --- gather + bilinear: warp wid handles v = vt + wid + 8k ---
            const float fu = (float)(u0 + lane) - 255.5f;
            const float fv = (float)(vt + wid) - 255.5f;
            float bx = fmaf(c, fu, fmaf(s, fv, 255.5f)) - (float)c_lo;
            float by = fmaf(-s, fu, fmaf(c, fv, 255.5f)) - (float)r_lo;

            #pragma unroll
            for (int k = 0; k < 8; ++k) {
                float s0, s1;
                {   // u = u0 + lane
                    const float fx0 = floorf(bx);
                    const float fy0 = floorf(by);
                    const float fx = bx - fx0;
                    const float fy = by - fy0;
                    const int idx = (int)fmaf(fy0, (float)PITCH, fx0);
                    const float v00 = tile[idx];
                    const float v01 = tile[idx + 1];
                    const float v10 = tile[idx + PITCH];
                    const float v11 = tile[idx + PITCH + 1];
                    const float top = fmaf(fx, v01 - v00, v00);
                    const float bot = fmaf(fx, v11 - v10, v10);
                    s0 = fmaf(fy, bot - top, top);
                }
                {   // u = u0 + 32 + lane
                    const float ix = bx + dux;
                    const float iy = by + duy;
                    const float fx0 = floorf(ix);
                    const float fy0 = floorf(iy);
                    const float fx = ix - fx0;
                    const float fy = iy - fy0;
                    const int idx = (int)fmaf(fy0, (float)PITCH, fx0);
                    const float v00 = tile[idx];
                    const float v01 = tile[idx + 1];
                    const float v10 = tile[idx + PITCH];
                    const float v11 = tile[idx + PITCH + 1];
                    const float top = fmaf(fx, v01 - v00, v00);
                    const float bot = fmaf(fx, v11 - v10, v10);
                    s1 = fmaf(fy, bot - top, top);
                }
                acc0 += s0;
                acc1 += s1;

                // v-sum across the 64 u's of this tile at v = vt + wid + 8k
                float pv = s0 + s1;
                #pragma unroll
                for (int m = 16; m > 0; m >>= 1)
                    pv += __shfl_xor_sync(0xffffffffu, pv, m);
                if (lane == 0) vsum[vt + wid + 8 * k] += pv;

                bx += dvx;
                by += dvy;
            }
            __syncthreads();   // tile reused by next stage / scratch alias
        }

        // --- u-strip reduction (scratch aliases tile region) ---
        tile[lane * 8 + wid]        = acc0;
        tile[(32 + lane) * 8 + wid] = acc1;
        __syncthreads();
        if (tid < TT) {
            const float* p = tile + tid * 8;
            const float tot = ((p[0] + p[1]) + (p[2] + p[3])) +
                              ((p[4] + p[5]) + (p[6] + p[7]));
            out[((size_t)(n * Ww + (u0 + tid))) * NA + a] = tot;
        }
        __syncthreads();
    }

    // --- paired angle: sino[a+90][b] = vsum[511 - b] ---
    for (int i = tid; i < 512; i += THREADS)
        out[((size_t)(n * Ww + (511 - i))) * NA + (a + 90)] = vsum[i];
}

extern "C" void kernel_launch(void* const* d_in, const int* in_sizes, int n_in,
                              void* d_out, int out_size) {
    (void)in_sizes; (void)n_in; (void)out_size;
    const float* x = (const float*)d_in[0];
    float* out = (float*)d_out;

    cudaFuncSetAttribute(radon_kernel,
                         cudaFuncAttributeMaxDynamicSharedMemorySize,
                         SMEM_BYTES);

    dim3 grid(90, 32);   // (angle pair, image)
    radon_kernel<<<grid, THREADS, SMEM_BYTES>>>(x, out);
}

// round 6
// speedup vs baseline: 6.9644x; 1.1611x over previous
#include <cuda_runtime.h>
#include <cuda_fp16.h>
#include <cstdint>

// Radon transform, ray-driven bilinear, matching the JAX reference
// (zero-filled SMEM sampling == reference's per-corner valid masking).
//
// x: (32, 1, 512, 512) f32   ->  out: (32, 1, 512, 180) f32
//
// 90-degree symmetry (R4): theta-sampled rotated image gives BOTH
//   sino[theta][u]    = row sums  (over v)
//   sino[theta+90][b] = column sums (over u) at v = 511-b
//
// R6 change vs R5 (L1/LSU-wavefront bound at 81.8%, issue 63.2%):
//   tile stored as fp16 VERTICAL PAIRS: word(p,c) = half2(row p, row p+1).
//   A bilinear sample reads 2 adjacent words (2 LDS) instead of 4 LDS;
//   x-lerp via one HSUB2+HFMA2 (top/bot lanes together), y-lerp in fp32.
//   Staging: register-carry row loads (each row loaded once, used by two
//   pair-rows), f32->f16x2 pack, STS. Tile 93x95 half2-words = 34.5KB ->
//   6 blocks/SM kept.

namespace {
constexpr int Hh = 512;
constexpr int Ww = 512;
constexpr int NA = 180;
constexpr int TT = 64;            // tile size in u and v
constexpr int PITCH = 95;         // words per pair-row (odd), cols <= 94
constexpr int PAIR_ROWS = 93;     // pair-rows <= 93
constexpr int TILE_WORDS = PAIR_ROWS * PITCH;       // 8835 half2-words
constexpr int THREADS = 256;                        // 8 warps
constexpr int SMEM_BYTES = (TILE_WORDS + 512) * 4;  // tile + vsum = 37388 B
}

// pack two f32 into f16x2: lo = f16(lo_f) (row p), hi = f16(hi_f) (row p+1)
__device__ __forceinline__ unsigned pack_h2(float hi_f, float lo_f) {
    unsigned d;
    asm("cvt.rn.f16x2.f32 %0, %1, %2;" : "=r"(d) : "f"(hi_f), "f"(lo_f));
    return d;
}

__global__ __launch_bounds__(THREADS, 6)
void radon_kernel(const float* __restrict__ x, float* __restrict__ out) {
    extern __shared__ float sm[];
    unsigned* tilew = (unsigned*)sm;        // 8835 half2 words (aliased scratch)
    float* vsum = sm + TILE_WORDS;          // 512 floats, persistent

    const int tid  = threadIdx.x;
    const int lane = tid & 31;
    const int wid  = tid >> 5;
    const int a    = blockIdx.x;   // 0..89
    const int n    = blockIdx.y;   // 0..31

    const float theta = (float)a * 0.017453292519943295f;
    float s, c;
    sincosf(theta, &s, &c);

    const float* __restrict__ img = x + (size_t)n * (size_t)(Hh * Ww);

    // zero v-accumulator (ordered before first gather by the staging barrier)
    for (int i = tid; i < 512; i += THREADS) vsum[i] = 0.0f;

    const float dux =  32.0f * c;   // ix step per +32 u
    const float duy = -32.0f * s;   // iy step per +32 u
    const float dvx =   8.0f * s;   // ix step per +8 v
    const float dvy =   8.0f * c;   // iy step per +8 v

    for (int ut = 0; ut < 8; ++ut) {
        const int u0 = ut * TT;
        const float fu_lo = (float)u0 - 255.5f;
        const float fu_hi = fu_lo + (float)(TT - 1);
        float acc0 = 0.f, acc1 = 0.f;

        for (int vt = 0; vt < Hh; vt += TT) {
            // --- bounding box of sample footprint for this (u,v) tile ---
            const float fv_lo = (float)vt - 255.5f;
            const float fv_hi = fv_lo + (float)(TT - 1);

            const float x00 = c * fu_lo + s * fv_lo, x01 = c * fu_lo + s * fv_hi;
            const float x10 = c * fu_hi + s * fv_lo, x11 = c * fu_hi + s * fv_hi;
            const float ixmin = fminf(fminf(x00, x01), fminf(x10, x11)) + 255.5f;
            const float ixmax = fmaxf(fmaxf(x00, x01), fmaxf(x10, x11)) + 255.5f;

            const float y00 = -s * fu_lo + c * fv_lo, y01 = -s * fu_lo + c * fv_hi;
            const float y10 = -s * fu_hi + c * fv_lo, y11 = -s * fu_hi + c * fv_hi;
            const float iymin = fminf(fminf(y00, y01), fminf(y10, y11)) + 255.5f;
            const float iymax = fmaxf(fmaxf(y00, y01), fmaxf(y10, y11)) + 255.5f;

            const int c_lo = (int)floorf(ixmin) - 1;
            const int cols = ((int)floorf(ixmax) + 2) - c_lo + 1;   // <= 94
            const int r_lo = (int)floorf(iymin) - 1;
            const int rows = ((int)floorf(iymax) + 2) - r_lo + 1;   // <= 94
            const int prs  = rows - 1;                              // <= 93

            // per-warp contiguous pair-row block (register row-carry)
            const int npr   = (prs + 7) >> 3;
            const int pr_lo = wid * npr;
            const int pr_hi = min(pr_lo + npr, prs);

            const bool interior = (c_lo >= 0) & (c_lo + cols <= Ww) &
                                  (r_lo >= 0) & (r_lo + rows <= Hh);

            if (pr_lo < pr_hi) {
                const bool ok1 = (lane + 32 < cols);
                const bool ok2 = (lane + 64 < cols);
                if (interior) {
                    const float* srcp = img + (size_t)(r_lo + pr_lo) * Ww
                                        + c_lo + lane;
                    float p0 = srcp[0];
                    float p1 = ok1 ? srcp[32] : 0.f;
                    float p2 = ok2 ? srcp[64] : 0.f;
                    for (int pr = pr_lo; pr < pr_hi; ++pr) {
                        srcp += Ww;
                        const float c0 = srcp[0];
                        const float c1 = ok1 ? srcp[32] : 0.f;
                        const float c2 = ok2 ? srcp[64] : 0.f;
                        unsigned* d = tilew + pr * PITCH + lane;
                        d[0] = pack_h2(c0, p0);
                        if (ok1) d[32] = pack_h2(c1, p1);
                        if (ok2) d[64] = pack_h2(c2, p2);
                        p0 = c0; p1 = c1; p2 = c2;
                    }
                } else {
                    const int g0 = c_lo + lane;
                    const int g1 = g0 + 32;
                    const int g2 = g0 + 64;
                    const bool c0ok = ((unsigned)g0 < (unsigned)Ww);
                    const bool c1ok = ok1 && ((unsigned)g1 < (unsigned)Ww);
                    const bool c2ok = ok2 && ((unsigned)g2 < (unsigned)Ww);
                    const int gc0 = min(max(g0, 0), Ww - 1);
                    const int gc1 = min(max(g1, 0), Ww - 1);
                    const int gc2 = min(max(g2, 0), Ww - 1);

                    int gr = r_lo + pr_lo;
                    bool rok = ((unsigned)gr < (unsigned)Hh);
                    const float* srcp =
                        img + (size_t)min(max(gr, 0), Hh - 1) * Ww;
                    float p0 = (rok & c0ok) ? srcp[gc0] : 0.f;
                    float p1 = (rok & c1ok) ? srcp[gc1] : 0.f;
                    float p2 = (rok & c2ok) ? srcp[gc2] : 0.f;
                    for (int pr = pr_lo; pr < pr_hi; ++pr) {
                        gr = r_lo + pr + 1;
                        rok = ((unsigned)gr < (unsigned)Hh);
                        srcp = img + (size_t)min(max(gr, 0), Hh - 1) * Ww;
                        const float c0 = (rok & c0ok) ? srcp[gc0] : 0.f;
                        const float c1 = (rok & c1ok) ? srcp[gc1] : 0.f;
                        const float c2 = (rok & c2ok) ? srcp[gc2] : 0.f;
                        unsigned* d = tilew + pr * PITCH + lane;
                        d[0] = pack_h2(c0, p0);
                        if (ok1) d[32] = pack_h2(c1, p1);
                        if (ok2) d[64] = pack_h2(c2, p2);
                        p0 = c0; p1 = c1; p2 = c2;
                    }
                }
            }
            __syncthreads();

            // --- gather + bilinear: warp wid handles v = vt + wid + 8k ---
            const __half2* tp = (const __half2*)tilew;
            const float fu = (float)(u0 + lane) - 255.5f;
            const float fv = (float)(vt + wid) - 255.5f;
            float bx = fmaf(c, fu, fmaf(s, fv, 255.5f)) - (float)c_lo;
            float by = fmaf(-s, fu, fmaf(c, fv, 255.5f)) - (float)r_lo;

            #pragma unroll
            for (int k = 0; k < 8; ++k) {
                float s0, s1;
                {   // u = u0 + lane
                    const float fx0 = floorf(bx);
                    const float fy0 = floorf(by);
                    const float fx = bx - fx0;
                    const float fy = by - fy0;
                    const int idx = (int)fmaf(fy0, (float)PITCH, fx0);
                    const __half2 w0 = tp[idx];       // (v00, v10)
                    const __half2 w1 = tp[idx + 1];   // (v01, v11)
                    const __half2 fx2 = __float2half2_rn(fx);
                    const __half2 tb = __hfma2(fx2, __hsub2(w1, w0), w0);
                    const float top = __low2float(tb);
                    const float bot = __high2float(tb);
                    s0 = fmaf(fy, bot - top, top);
                }
                {   // u = u0 + 32 + lane
                    const float ix = bx + dux;
                    const float iy = by + duy;
                    const float fx0 = floorf(ix);
                    const float fy0 = floorf(iy);
                    const float fx = ix - fx0;
                    const float fy = iy - fy0;
                    const int idx = (int)fmaf(fy0, (float)PITCH, fx0);
                    const __half2 w0 = tp[idx];
                    const __half2 w1 = tp[idx + 1];
                    const __half2 fx2 = __float2half2_rn(fx);
                    const __half2 tb = __hfma2(fx2, __hsub2(w1, w0), w0);
                    const float top = __low2float(tb);
                    const float bot = __high2float(tb);
                    s1 = fmaf(fy, bot - top, top);
                }
                acc0 += s0;
                acc1 += s1;

                // v-sum across the 64 u's of this tile at v = vt + wid + 8k
                float pv = s0 + s1;
                #pragma unroll
                for (int m = 16; m > 0; m >>= 1)
                    pv += __shfl_xor_sync(0xffffffffu, pv, m);
                if (lane == 0) vsum[vt + wid + 8 * k] += pv;

                bx += dvx;
                by += dvy;
            }
            __syncthreads();   // tile reused by next stage / scratch alias
        }

        // --- u-strip reduction (scratch aliases tile region) ---
        float* scratch = (float*)tilew;
        scratch[lane * 8 + wid]        = acc0;
        scratch[(32 + lane) * 8 + wid] = acc1;
        __syncthreads();
        if (tid < TT) {
            const float* p = scratch + tid * 8;
            const float tot = ((p[0] + p[1]) + (p[2] + p[3])) +
                              ((p[4] + p[5]) + (p[6] + p[7]));
            out[((size_t)(n * Ww + (u0 + tid))) * NA + a] = tot;
        }
        __syncthreads();
    }

    // --- paired angle: sino[a+90][b] = vsum[511 - b] ---
    for (int i = tid; i < 512; i += THREADS)
        out[((size_t)(n * Ww + (511 - i))) * NA + (a + 90)] = vsum[i];
}

extern "C" void kernel_launch(void* const* d_in, const int* in_sizes, int n_in,
                              void* d_out, int out_size) {
    (void)in_sizes; (void)n_in; (void)out_size;
    const float* x = (const float*)d_in[0];
    float* out = (float*)d_out;

    cudaFuncSetAttribute(radon_kernel,
                         cudaFuncAttributeMaxDynamicSharedMemorySize,
                         SMEM_BYTES);

    dim3 grid(90, 32);   // (angle pair, image)
    radon_kernel<<<grid, THREADS, SMEM_BYTES>>>(x, out);
}

// round 7
// speedup vs baseline: 7.3420x; 1.0542x over previous
#include <cuda_runtime.h>
#include <cuda_fp16.h>
#include <cstdint>

// Radon transform, ray-driven bilinear, matching the JAX reference
// (zero-filled SMEM sampling == reference's per-corner valid masking).
//
// x: (32, 1, 512, 512) f32   ->  out: (32, 1, 512, 180) f32
//
// 90-degree symmetry (R4): theta-sampled rotated image gives BOTH
//   sino[theta][u]    = row sums  (over v)
//   sino[theta+90][b] = column sums (over u) at v = 511-b
// fp16 vertical-pair tile (R6): 2 LDS per bilinear sample.
//
// R7 changes vs R6 (wave-tail ~23% at grid 2880 / 888 slots):
//  - grid (90,32,2): each block does 4 u-strips -> 5760 blocks, tail ~8%.
//    Column sums get exactly 2 atomicAdd contributors (commutative -> still
//    deterministic); out zeroed by cudaMemsetAsync before the kernel.
//  - tiles whose bbox misses the image entirely are skipped (contribution
//    is exactly zero under the reference's corner masking).

namespace {
constexpr int Hh = 512;
constexpr int Ww = 512;
constexpr int NA = 180;
constexpr int TT = 64;            // tile size in u and v
constexpr int PITCH = 95;         // words per pair-row (odd), cols <= 94
constexpr int PAIR_ROWS = 93;     // pair-rows <= 93
constexpr int TILE_WORDS = PAIR_ROWS * PITCH;       // 8835 half2-words
constexpr int THREADS = 256;                        // 8 warps
constexpr int SMEM_BYTES = (TILE_WORDS + 512) * 4;  // tile + vsum = 37388 B
constexpr int UT_PER_BLOCK = 4;
}

// pack two f32 into f16x2: lo = f16(lo_f) (row p), hi = f16(hi_f) (row p+1)
__device__ __forceinline__ unsigned pack_h2(float hi_f, float lo_f) {
    unsigned d;
    asm("cvt.rn.f16x2.f32 %0, %1, %2;" : "=r"(d) : "f"(hi_f), "f"(lo_f));
    return d;
}

__global__ __launch_bounds__(THREADS, 6)
void radon_kernel(const float* __restrict__ x, float* __restrict__ out) {
    extern __shared__ float sm[];
    unsigned* tilew = (unsigned*)sm;        // 8835 half2 words (aliased scratch)
    float* vsum = sm + TILE_WORDS;          // 512 floats, persistent

    const int tid  = threadIdx.x;
    const int lane = tid & 31;
    const int wid  = tid >> 5;
    const int a    = blockIdx.x;   // 0..89
    const int n    = blockIdx.y;   // 0..31
    const int z    = blockIdx.z;   // 0..1: u-half

    const float theta = (float)a * 0.017453292519943295f;
    float s, c;
    sincosf(theta, &s, &c);

    const float* __restrict__ img = x + (size_t)n * (size_t)(Hh * Ww);

    // zero v-accumulator (ordered before first gather by the staging barrier)
    for (int i = tid; i < 512; i += THREADS) vsum[i] = 0.0f;

    const float dux =  32.0f * c;   // ix step per +32 u
    const float duy = -32.0f * s;   // iy step per +32 u
    const float dvx =   8.0f * s;   // ix step per +8 v
    const float dvy =   8.0f * c;   // iy step per +8 v

    for (int ut = 0; ut < UT_PER_BLOCK; ++ut) {
        const int u0 = (z * UT_PER_BLOCK + ut) * TT;
        const float fu_lo = (float)u0 - 255.5f;
        const float fu_hi = fu_lo + (float)(TT - 1);
        float acc0 = 0.f, acc1 = 0.f;

        for (int vt = 0; vt < Hh; vt += TT) {
            // --- bounding box of sample footprint for this (u,v) tile ---
            const float fv_lo = (float)vt - 255.5f;
            const float fv_hi = fv_lo + (float)(TT - 1);

            const float x00 = c * fu_lo + s * fv_lo, x01 = c * fu_lo + s * fv_hi;
            const float x10 = c * fu_hi + s * fv_lo, x11 = c * fu_hi + s * fv_hi;
            const float ixmin = fminf(fminf(x00, x01), fminf(x10, x11)) + 255.5f;
            const float ixmax = fmaxf(fmaxf(x00, x01), fmaxf(x10, x11)) + 255.5f;

            const float y00 = -s * fu_lo + c * fv_lo, y01 = -s * fu_lo + c * fv_hi;
            const float y10 = -s * fu_hi + c * fv_lo, y11 = -s * fu_hi + c * fv_hi;
            const float iymin = fminf(fminf(y00, y01), fminf(y10, y11)) + 255.5f;
            const float iymax = fmaxf(fmaxf(y00, y01), fmaxf(y10, y11)) + 255.5f;

            const int c_lo = (int)floorf(ixmin) - 1;
            const int cols = ((int)floorf(ixmax) + 2) - c_lo + 1;   // <= 94
            const int r_lo = (int)floorf(iymin) - 1;
            const int rows = ((int)floorf(iymax) + 2) - r_lo + 1;   // <= 94
            const int prs  = rows - 1;                              // <= 93

            // tile entirely outside the image -> contribution is exactly 0
            // (block-uniform predicate: barrier-safe skip)
            if ((c_lo >= Ww) | (r_lo >= Hh) |
                (c_lo + cols <= 0) | (r_lo + rows <= 0))
                continue;

            // per-warp contiguous pair-row block (register row-carry)
            const int npr   = (prs + 7) >> 3;
            const int pr_lo = wid * npr;
            const int pr_hi = min(pr_lo + npr, prs);

            const bool interior = (c_lo >= 0) & (c_lo + cols <= Ww) &
                                  (r_lo >= 0) & (r_lo + rows <= Hh);

            if (pr_lo < pr_hi) {
                const bool ok1 = (lane + 32 < cols);
                const bool ok2 = (lane + 64 < cols);
                if (interior) {
                    const float* srcp = img + (size_t)(r_lo + pr_lo) * Ww
                                        + c_lo + lane;
                    float p0 = srcp[0];
                    float p1 = ok1 ? srcp[32] : 0.f;
                    float p2 = ok2 ? srcp[64] : 0.f;
                    for (int pr = pr_lo; pr < pr_hi; ++pr) {
                        srcp += Ww;
                        const float c0 = srcp[0];
                        const float c1 = ok1 ? srcp[32] : 0.f;
                        const float c2 = ok2 ? srcp[64] : 0.f;
                        unsigned* d = tilew + pr * PITCH + lane;
                        d[0] = pack_h2(c0, p0);
                        if (ok1) d[32] = pack_h2(c1, p1);
                        if (ok2) d[64] = pack_h2(c2, p2);
                        p0 = c0; p1 = c1; p2 = c2;
                    }
                } else {
                    const int g0 = c_lo + lane;
                    const int g1 = g0 + 32;
                    const int g2 = g0 + 64;
                    const bool c0ok = ((unsigned)g0 < (unsigned)Ww);
                    const bool c1ok = ok1 && ((unsigned)g1 < (unsigned)Ww);
                    const bool c2ok = ok2 && ((unsigned)g2 < (unsigned)Ww);
                    const int gc0 = min(max(g0, 0), Ww - 1);
                    const int gc1 = min(max(g1, 0), Ww - 1);
                    const int gc2 = min(max(g2, 0), Ww - 1);

                    int gr = r_lo + pr_lo;
                    bool rok = ((unsigned)gr < (unsigned)Hh);
                    const float* srcp =
                        img + (size_t)min(max(gr, 0), Hh - 1) * Ww;
                    float p0 = (rok & c0ok) ? srcp[gc0] : 0.f;
                    float p1 = (rok & c1ok) ? srcp[gc1] : 0.f;
                    float p2 = (rok & c2ok) ? srcp[gc2] : 0.f;
                    for (int pr = pr_lo; pr < pr_hi; ++pr) {
                        gr = r_lo + pr + 1;
                        rok = ((unsigned)gr < (unsigned)Hh);
                        srcp = img + (size_t)min(max(gr, 0), Hh - 1) * Ww;
                        const float c0 = (rok & c0ok) ? srcp[gc0] : 0.f;
                        const float c1 = (rok & c1ok) ? srcp[gc1] : 0.f;
                        const float c2 = (rok & c2ok) ? srcp[gc2] : 0.f;
                        unsigned* d = tilew + pr * PITCH + lane;
                        d[0] = pack_h2(c0, p0);
                        if (ok1) d[32] = pack_h2(c1, p1);
                        if (ok2) d[64] = pack_h2(c2, p2);
                        p0 = c0; p1 = c1; p2 = c2;
                    }
                }
            }
            __syncthreads();

            // --- gather + bilinear: warp wid handles v = vt + wid + 8k ---
            const __half2* tp = (const __half2*)tilew;
            const float fu = (float)(u0 + lane) - 255.5f;
            const float fv = (float)(vt + wid) - 255.5f;
            float bx = fmaf(c, fu, fmaf(s, fv, 255.5f)) - (float)c_lo;
            float by = fmaf(-s, fu, fmaf(c, fv, 255.5f)) - (float)r_lo;

            #pragma unroll
            for (int k = 0; k < 8; ++k) {
                float s0, s1;
                {   // u = u0 + lane
                    const float fx0 = floorf(bx);
                    const float fy0 = floorf(by);
                    const float fx = bx - fx0;
                    const float fy = by - fy0;
                    const int idx = (int)fmaf(fy0, (float)PITCH, fx0);
                    const __half2 w0 = tp[idx];       // (v00, v10)
                    const __half2 w1 = tp[idx + 1];   // (v01, v11)
                    const __half2 fx2 = __float2half2_rn(fx);
                    const __half2 tb = __hfma2(fx2, __hsub2(w1, w0), w0);
                    const float top = __low2float(tb);
                    const float bot = __high2float(tb);
                    s0 = fmaf(fy, bot - top, top);
                }
                {   // u = u0 + 32 + lane
                    const float ix = bx + dux;
                    const float iy = by + duy;
                    const float fx0 = floorf(ix);
                    const float fy0 = floorf(iy);
                    const float fx = ix - fx0;
                    const float fy = iy - fy0;
                    const int idx = (int)fmaf(fy0, (float)PITCH, fx0);
                    const __half2 w0 = tp[idx];
                    const __half2 w1 = tp[idx + 1];
                    const __half2 fx2 = __float2half2_rn(fx);
                    const __half2 tb = __hfma2(fx2, __hsub2(w1, w0), w0);
                    const float top = __low2float(tb);
                    const float bot = __high2float(tb);
                    s1 = fmaf(fy, bot - top, top);
                }
                acc0 += s0;
                acc1 += s1;

                // v-sum across the 64 u's of this tile at v = vt + wid + 8k
                float pv = s0 + s1;
                #pragma unroll
                for (int m = 16; m > 0; m >>= 1)
                    pv += __shfl_xor_sync(0xffffffffu, pv, m);
                if (lane == 0) vsum[vt + wid + 8 * k] += pv;

                bx += dvx;
                by += dvy;
            }
            __syncthreads();   // tile reused by next stage / scratch alias
        }

        // --- u-strip reduction (scratch aliases tile region) ---
        float* scratch = (float*)tilew;
        scratch[lane * 8 + wid]        = acc0;
        scratch[(32 + lane) * 8 + wid] = acc1;
        __syncthreads();
        if (tid < TT) {
            const float* p = scratch + tid * 8;
            const float tot = ((p[0] + p[1]) + (p[2] + p[3])) +
                              ((p[4] + p[5]) + (p[6] + p[7]));
            out[((size_t)(n * Ww + (u0 + tid))) * NA + a] = tot;
        }
        __syncthreads();
    }

    // --- paired angle: sino[a+90][b] += vsum[511 - b] (2 contributors,
    //     commutative fp add -> deterministic) ---
    for (int i = tid; i < 512; i += THREADS)
        atomicAdd(&out[((size_t)(n * Ww + (511 - i))) * NA + (a + 90)],
                  vsum[i]);
}

extern "C" void kernel_launch(void* const* d_in, const int* in_sizes, int n_in,
                              void* d_out, int out_size) {
    (void)in_sizes; (void)n_in;
    const float* x = (const float*)d_in[0];
    float* out = (float*)d_out;

    cudaFuncSetAttribute(radon_kernel,
                         cudaFuncAttributeMaxDynamicSharedMemorySize,
                         SMEM_BYTES);

    cudaMemsetAsync(out, 0, (size_t)out_size * sizeof(float), 0);

    dim3 grid(90, 32, 2);   // (angle pair, image, u-half)
    radon_kernel<<<grid, THREADS, SMEM_BYTES>>>(x, out);
}